// round 2
// baseline (speedup 1.0000x reference)
#include <cuda_runtime.h>

#define NN 8192
#define HH 16
#define NHEAD 4
#define SLICES 8
#define TILE 256

#define DMAX 10
#define NF 1001              // number of multi-indices |alpha| <= 10 in dim 4 = C(14,4)
#define GRIDA 64
#define KEYS_PER_BLK (NN / GRIDA)   // 128
#define S_MAX 2.0f

// ---------------- device scratch (no allocations allowed) ----------------
__device__ float  g_Hseq[NN * HH];            // LSTM hidden states
__device__ float4 g_Q[NN * NHEAD];            // pre-scaled queries (x 0.5)
__device__ float4 g_K[NN * NHEAD];
__device__ float4 g_V[NN * NHEAD];

__device__ float  g_prepA[GRIDA][24];         // 16 ksum, 4 maxk2, 4 maxq2
__device__ float  g_kbar[NHEAD][4];
__device__ int    g_flag;                     // 1 = Taylor path valid
__device__ float  g_invfact[NF];
__device__ unsigned g_alpha[NF];

__device__ float  g_Mpart[GRIDA][NHEAD][NF][5];
__device__ float  g_M[NHEAD][NF * 5];
__device__ float4 g_ctx[NN * NHEAD];          // Taylor-path context (already normalized)

__device__ float  g_Pden[SLICES * NN * NHEAD];   // fallback partial denominators
__device__ float4 g_Pctx[SLICES * NN * NHEAD];   // fallback partial weighted V sums
__device__ float  g_Pblk[32 * 3];                // per-block readout partial sums

// ---------------- kernel 1: serial LSTM, one warp (unchanged numerics) ----
__global__ void lstm_kernel(const float* __restrict__ t,
                            const float* __restrict__ W_ih,
                            const float* __restrict__ W_hh,
                            const float* __restrict__ b_ih,
                            const float* __restrict__ b_hh) {
    __shared__ float tsh[NN];
    const int lane = threadIdx.x;
    for (int i = lane; i < NN; i += 32) tsh[i] = t[i];

    const int r1 = lane, r2 = lane + 32;
    float w1[HH], w2[HH];
#pragma unroll
    for (int k = 0; k < HH; k++) {
        w1[k] = W_hh[r1 * HH + k];
        w2[k] = W_hh[r2 * HH + k];
    }
    const float wi1 = W_ih[r1], wi2 = W_ih[r2];
    const float bb1 = b_ih[r1] + b_hh[r1];
    const float bb2 = b_ih[r2] + b_hh[r2];

    float h[HH];
#pragma unroll
    for (int k = 0; k < HH; k++) h[k] = 0.0f;
    float c = 0.0f;
    const bool lo = (lane < 16);
    const int peer = (lane & 15) + 16;

    __syncwarp();

    for (int step = 0; step < NN; step++) {
        const float x = tsh[step];
        float g1a = fmaf(wi1, x, bb1), g1b = 0.0f;
        float g2a = fmaf(wi2, x, bb2), g2b = 0.0f;
#pragma unroll
        for (int k = 0; k < HH; k += 2) {
            g1a = fmaf(w1[k],     h[k],     g1a);
            g1b = fmaf(w1[k + 1], h[k + 1], g1b);
            g2a = fmaf(w2[k],     h[k],     g2a);
            g2b = fmaf(w2[k + 1], h[k + 1], g2b);
        }
        const float g1 = g1a + g1b;
        const float g2 = g2a + g2b;

        const float a1 = __fdividef(1.0f, 1.0f + __expf(-g1));
        const float s2 = lo ? (2.0f * g2) : g2;
        const float e2 = __fdividef(1.0f, 1.0f + __expf(-s2));
        const float a2 = lo ? fmaf(2.0f, e2, -1.0f) : e2;

        const float fg = __shfl_sync(0xffffffffu, a1, peer);
        const float og = __shfl_sync(0xffffffffu, a2, peer);

        c = fmaf(fg, c, a1 * a2);
        const float ec = __fdividef(1.0f, 1.0f + __expf(-2.0f * c));
        const float tc = fmaf(2.0f, ec, -1.0f);
        const float hn = og * tc;

        if (lane < 16) g_Hseq[step * HH + lane] = hn;

#pragma unroll
        for (int k = 0; k < HH; k++)
            h[k] = __shfl_sync(0xffffffffu, hn, k);
    }
}

// ---------------- kernel 2: QKV projection ----------------
__global__ void qkv_kernel(const float* __restrict__ in_proj_w,
                           const float* __restrict__ in_proj_b) {
    const int idx = blockIdx.x * blockDim.x + threadIdx.x;
    if (idx >= NN * 48) return;
    const int n = idx / 48;
    const int j = idx % 48;
    const float* hr = g_Hseq + n * HH;
    float acc = in_proj_b[j];
#pragma unroll
    for (int k = 0; k < HH; k++)
        acc = fmaf(__ldg(in_proj_w + j * HH + k), hr[k], acc);

    if (j < 16)       ((float*)g_Q)[n * HH + j]        = acc * 0.5f;  // 1/sqrt(HD)
    else if (j < 32)  ((float*)g_K)[n * HH + (j - 16)] = acc;
    else              ((float*)g_V)[n * HH + (j - 32)] = acc;
}

// ---------------- kernel 3a: per-block stats (deterministic) --------------
__global__ void prepA_kernel() {
    __shared__ float red[256][25];
    const int tid = threadIdx.x;
    const int blk = blockIdx.x;

    float ks[16];
#pragma unroll
    for (int i = 0; i < 16; i++) ks[i] = 0.0f;
    float mk2[4] = {0.f, 0.f, 0.f, 0.f};
    float mq2[4] = {0.f, 0.f, 0.f, 0.f};

    for (int i = tid; i < KEYS_PER_BLK; i += 256) {
        const int n = blk * KEYS_PER_BLK + i;
#pragma unroll
        for (int h = 0; h < NHEAD; h++) {
            const float4 k = g_K[n * NHEAD + h];
            ks[h * 4 + 0] += k.x; ks[h * 4 + 1] += k.y;
            ks[h * 4 + 2] += k.z; ks[h * 4 + 3] += k.w;
            const float kk = k.x * k.x + k.y * k.y + k.z * k.z + k.w * k.w;
            mk2[h] = fmaxf(mk2[h], kk);
            const float4 q = g_Q[n * NHEAD + h];
            const float qq = q.x * q.x + q.y * q.y + q.z * q.z + q.w * q.w;
            mq2[h] = fmaxf(mq2[h], qq);
        }
    }
#pragma unroll
    for (int i = 0; i < 16; i++) red[tid][i] = ks[i];
#pragma unroll
    for (int h = 0; h < 4; h++) { red[tid][16 + h] = mk2[h]; red[tid][20 + h] = mq2[h]; }
    __syncthreads();

    if (tid < 24) {
        float r = red[0][tid];
        if (tid < 16) { for (int i = 1; i < 256; i++) r += red[i][tid]; }
        else          { for (int i = 1; i < 256; i++) r = fmaxf(r, red[i][tid]); }
        g_prepA[blk][tid] = r;
    }
}

// ---------------- kernel 3b: combine stats, bound check, tables -----------
__global__ void prepB_kernel() {
    __shared__ float s[24];
    const int t = threadIdx.x;
    if (t < 24) {
        float r = g_prepA[0][t];
        if (t < 16) { for (int b = 1; b < GRIDA; b++) r += g_prepA[b][t]; }
        else        { for (int b = 1; b < GRIDA; b++) r = fmaxf(r, g_prepA[b][t]); }
        s[t] = r;
    }
    __syncthreads();

    if (t == 0) {
        float kbar[16];
#pragma unroll
        for (int i = 0; i < 16; i++) {
            kbar[i] = s[i] * (1.0f / (float)NN);
            ((float*)g_kbar)[i] = kbar[i];
        }
        float bound = 0.0f;
#pragma unroll
        for (int h = 0; h < NHEAD; h++) {
            const float kb = sqrtf(kbar[h*4]*kbar[h*4] + kbar[h*4+1]*kbar[h*4+1]
                                 + kbar[h*4+2]*kbar[h*4+2] + kbar[h*4+3]*kbar[h*4+3]);
            const float bk = sqrtf(s[16 + h]) + kb;     // |k - kbar| <= |k|max + |kbar|
            const float bq = sqrtf(s[20 + h]);          // max |q_scaled|
            bound = fmaxf(bound, bq * bk);
        }
        g_flag = (bound <= S_MAX) ? 1 : 0;

        // tables: alpha enumeration + 1/alpha!
        float fact[DMAX + 1];
        fact[0] = 1.0f;
        for (int n = 1; n <= DMAX; n++) fact[n] = fact[n - 1] * (float)n;
        float invt[DMAX + 1];
        for (int n = 0; n <= DMAX; n++) invt[n] = 1.0f / fact[n];
        int idx = 0;
        for (int a = 0; a <= DMAX; a++)
            for (int b = 0; b <= DMAX - a; b++)
                for (int c = 0; c <= DMAX - a - b; c++)
                    for (int d = 0; d <= DMAX - a - b - c; d++) {
                        g_alpha[idx] = (unsigned)a | ((unsigned)b << 8)
                                     | ((unsigned)c << 16) | ((unsigned)d << 24);
                        g_invfact[idx] = invt[a] * invt[b] * invt[c] * invt[d];
                        idx++;
                    }
    }
}

// ---------------- kernel 4: Taylor aggregation over keys ------------------
// Block = 1024 threads, thread tid owns feature alpha_tid; 64 blocks over keys.
__global__ void __launch_bounds__(1024, 1) agg_kernel() {
    if (g_flag == 0) return;

    __shared__ float4 Kt[KEYS_PER_BLK][NHEAD];
    __shared__ float4 Vt[KEYS_PER_BLK][NHEAD];
    __shared__ float4 pow4[2][4][DMAX + 1];   // [buf][var][deg], float4 over heads

    const int tid = threadIdx.x;
    const int blk = blockIdx.x;
    const int base = blk * KEYS_PER_BLK * NHEAD;

    if (tid < KEYS_PER_BLK * NHEAD) {
        ((float4*)Kt)[tid] = g_K[base + tid];
        ((float4*)Vt)[tid] = g_V[base + tid];
    }

    // pow builders: threads 0..15 -> (head = tid&3, var = tid>>2)
    float kb = 0.0f;
    const int bh = tid & 3, bvar = tid >> 2;
    if (tid < 16) kb = g_kbar[bh][bvar];

    const unsigned al = g_alpha[(tid < NF) ? tid : 0];
    const int fa = (int)(al & 255u);
    const int fb = (int)((al >> 8) & 255u);
    const int fc = (int)((al >> 16) & 255u);
    const int fd = (int)(al >> 24);

    float acc00 = 0, acc01 = 0, acc02 = 0, acc03 = 0, den0 = 0;
    float acc10 = 0, acc11 = 0, acc12 = 0, acc13 = 0, den1 = 0;
    float acc20 = 0, acc21 = 0, acc22 = 0, acc23 = 0, den2 = 0;
    float acc30 = 0, acc31 = 0, acc32 = 0, acc33 = 0, den3 = 0;

    __syncthreads();

    for (int key = 0; key < KEYS_PER_BLK; key++) {
        const int bu = key & 1;
        if (tid < 16) {
            const float x = ((const float*)&Kt[key][bh])[bvar] - kb;
            float p = 1.0f;
#pragma unroll
            for (int deg = 0; deg <= DMAX; deg++) {
                ((float*)&pow4[bu][bvar][deg])[bh] = p;
                p *= x;
            }
        }
        __syncthreads();

        const float4 px = pow4[bu][0][fa];
        const float4 py = pow4[bu][1][fb];
        const float4 pz = pow4[bu][2][fc];
        const float4 pw = pow4[bu][3][fd];

        {
            const float m = px.x * py.x * pz.x * pw.x;
            const float4 v = Vt[key][0];
            acc00 = fmaf(m, v.x, acc00); acc01 = fmaf(m, v.y, acc01);
            acc02 = fmaf(m, v.z, acc02); acc03 = fmaf(m, v.w, acc03);
            den0 += m;
        }
        {
            const float m = px.y * py.y * pz.y * pw.y;
            const float4 v = Vt[key][1];
            acc10 = fmaf(m, v.x, acc10); acc11 = fmaf(m, v.y, acc11);
            acc12 = fmaf(m, v.z, acc12); acc13 = fmaf(m, v.w, acc13);
            den1 += m;
        }
        {
            const float m = px.z * py.z * pz.z * pw.z;
            const float4 v = Vt[key][2];
            acc20 = fmaf(m, v.x, acc20); acc21 = fmaf(m, v.y, acc21);
            acc22 = fmaf(m, v.z, acc22); acc23 = fmaf(m, v.w, acc23);
            den2 += m;
        }
        {
            const float m = px.w * py.w * pz.w * pw.w;
            const float4 v = Vt[key][3];
            acc30 = fmaf(m, v.x, acc30); acc31 = fmaf(m, v.y, acc31);
            acc32 = fmaf(m, v.z, acc32); acc33 = fmaf(m, v.w, acc33);
            den3 += m;
        }
    }

    if (tid < NF) {
        float* p0 = &g_Mpart[blk][0][tid][0];
        p0[0] = acc00; p0[1] = acc01; p0[2] = acc02; p0[3] = acc03; p0[4] = den0;
        float* p1 = &g_Mpart[blk][1][tid][0];
        p1[0] = acc10; p1[1] = acc11; p1[2] = acc12; p1[3] = acc13; p1[4] = den1;
        float* p2 = &g_Mpart[blk][2][tid][0];
        p2[0] = acc20; p2[1] = acc21; p2[2] = acc22; p2[3] = acc23; p2[4] = den2;
        float* p3 = &g_Mpart[blk][3][tid][0];
        p3[0] = acc30; p3[1] = acc31; p3[2] = acc32; p3[3] = acc33; p3[4] = den3;
    }
}

// ---------------- kernel 5: combine partials, fold 1/alpha! ---------------
__global__ void combine_kernel() {
    if (g_flag == 0) return;
    const int idx = blockIdx.x * 256 + threadIdx.x;
    if (idx >= NHEAD * NF * 5) return;
    const int j  = idx % 5;
    const int al = (idx / 5) % NF;
    const int h  = idx / (5 * NF);
    float sum = 0.0f;
#pragma unroll 4
    for (int b = 0; b < GRIDA; b++)
        sum += g_Mpart[b][h][al][j];
    g_M[h][al * 5 + j] = sum * g_invfact[al];
}

// ---------------- kernel 6: Taylor query pass ------------------------------
__global__ void tquery_kernel() {
    if (g_flag == 0) return;
    __shared__ float Msh[NF * 5];
    const int tid = threadIdx.x;
    const int h = blockIdx.y;
    for (int i = tid; i < NF * 5; i += 256) Msh[i] = g_M[h][i];
    __syncthreads();

    const int q = blockIdx.x * 256 + tid;
    const float4 qv = g_Q[q * NHEAD + h];

    float a0 = 0, a1 = 0, a2 = 0, a3 = 0, dn = 0;
    int idx = 0;
    float pa = 1.0f;
    for (int a = 0; a <= DMAX; a++) {
        float pab = pa;
        for (int b = 0; b <= DMAX - a; b++) {
            float pabc = pab;
            for (int c = 0; c <= DMAX - a - b; c++) {
                float m = pabc;
                for (int d = 0; d <= DMAX - a - b - c; d++) {
                    const float* Mp = &Msh[idx * 5];
                    a0 = fmaf(m, Mp[0], a0);
                    a1 = fmaf(m, Mp[1], a1);
                    a2 = fmaf(m, Mp[2], a2);
                    a3 = fmaf(m, Mp[3], a3);
                    dn = fmaf(m, Mp[4], dn);
                    idx++;
                    m *= qv.w;
                }
                pabc *= qv.z;
            }
            pab *= qv.y;
        }
        pa *= qv.x;
    }
    const float inv = __fdividef(1.0f, dn);
    g_ctx[q * NHEAD + h] = make_float4(a0 * inv, a1 * inv, a2 * inv, a3 * inv);
}

// ---------------- kernel 7: exact fallback attention (flag-gated) ---------
__global__ void attn_kernel() {
    if (g_flag != 0) return;
    __shared__ float4 Ksh[TILE * NHEAD];
    __shared__ float4 Vsh[TILE * NHEAD];

    const int tid = threadIdx.x;
    const int h   = tid >> 6;
    const int ql  = tid & 63;
    const int q   = blockIdx.x * 64 + ql;
    const int s   = blockIdx.y;

    const float4 qv = g_Q[q * NHEAD + h];
    float den = 0.0f;
    float4 acc = make_float4(0.0f, 0.0f, 0.0f, 0.0f);

    const int kbase0 = s * (NN / SLICES);
    for (int tile = 0; tile < (NN / SLICES) / TILE; tile++) {
        const int kb = kbase0 + tile * TILE;
        __syncthreads();
#pragma unroll
        for (int r = 0; r < 4; r++) {
            Ksh[tid + 256 * r] = g_K[kb * NHEAD + tid + 256 * r];
            Vsh[tid + 256 * r] = g_V[kb * NHEAD + tid + 256 * r];
        }
        __syncthreads();

#pragma unroll 4
        for (int kk = 0; kk < TILE; kk++) {
            const float4 kvv = Ksh[kk * NHEAD + h];
            float sc = qv.x * kvv.x;
            sc = fmaf(qv.y, kvv.y, sc);
            sc = fmaf(qv.z, kvv.z, sc);
            sc = fmaf(qv.w, kvv.w, sc);
            const float p = __expf(sc);
            den += p;
            const float4 vv = Vsh[kk * NHEAD + h];
            acc.x = fmaf(p, vv.x, acc.x);
            acc.y = fmaf(p, vv.y, acc.y);
            acc.z = fmaf(p, vv.z, acc.z);
            acc.w = fmaf(p, vv.w, acc.w);
        }
    }

    const int o = (s * NN + q) * NHEAD + h;
    g_Pden[o] = den;
    g_Pctx[o] = acc;
}

// ---------------- kernel 8: combine + out_proj + residual + LN + readout --
__global__ void finalize_kernel(const float* __restrict__ out_proj_w,
                                const float* __restrict__ out_proj_b,
                                const float* __restrict__ ln_w,
                                const float* __restrict__ ln_b,
                                const float* __restrict__ out_w) {
    const int q = blockIdx.x * 256 + threadIdx.x;
    const int flag = g_flag;

    float ctx[HH];
    if (flag) {
#pragma unroll
        for (int h = 0; h < NHEAD; h++) {
            const float4 cv = g_ctx[q * NHEAD + h];
            ctx[h * 4 + 0] = cv.x; ctx[h * 4 + 1] = cv.y;
            ctx[h * 4 + 2] = cv.z; ctx[h * 4 + 3] = cv.w;
        }
    } else {
#pragma unroll
        for (int h = 0; h < NHEAD; h++) {
            float den = 0.0f;
            float4 a = make_float4(0.0f, 0.0f, 0.0f, 0.0f);
#pragma unroll
            for (int s = 0; s < SLICES; s++) {
                const int o = (s * NN + q) * NHEAD + h;
                den += g_Pden[o];
                const float4 p = g_Pctx[o];
                a.x += p.x; a.y += p.y; a.z += p.z; a.w += p.w;
            }
            const float inv = __fdividef(1.0f, den);
            ctx[h * 4 + 0] = a.x * inv;
            ctx[h * 4 + 1] = a.y * inv;
            ctx[h * 4 + 2] = a.z * inv;
            ctx[h * 4 + 3] = a.w * inv;
        }
    }

    float y[HH];
#pragma unroll
    for (int r = 0; r < HH; r++) {
        float t = out_proj_b[r];
#pragma unroll
        for (int cc = 0; cc < HH; cc++)
            t = fmaf(__ldg(out_proj_w + r * HH + cc), ctx[cc], t);
        y[r] = t + g_Hseq[q * HH + r];
    }

    float mu = 0.0f;
#pragma unroll
    for (int r = 0; r < HH; r++) mu += y[r];
    mu *= (1.0f / HH);
    float var = 0.0f;
#pragma unroll
    for (int r = 0; r < HH; r++) {
        const float d = y[r] - mu;
        var = fmaf(d, d, var);
    }
    var *= (1.0f / HH);
    const float rstd = rsqrtf(var + 1e-5f);

    float z[HH];
#pragma unroll
    for (int r = 0; r < HH; r++)
        z[r] = (y[r] - mu) * rstd * ln_w[r] + ln_b[r];

    float raw[3];
#pragma unroll
    for (int j = 0; j < 3; j++) {
        float t = 0.0f;
#pragma unroll
        for (int r = 0; r < HH; r++)
            t = fmaf(__ldg(out_w + j * HH + r), z[r], t);
        raw[j] = t;
    }

    __shared__ float wsum[8][3];
    const int lane = threadIdx.x & 31;
    const int wid  = threadIdx.x >> 5;
#pragma unroll
    for (int j = 0; j < 3; j++) {
        float v = raw[j];
#pragma unroll
        for (int off = 16; off > 0; off >>= 1)
            v += __shfl_xor_sync(0xffffffffu, v, off);
        if (lane == 0) wsum[wid][j] = v;
    }
    __syncthreads();
    if (threadIdx.x < 3) {
        float v = 0.0f;
#pragma unroll
        for (int w = 0; w < 8; w++) v += wsum[w][threadIdx.x];
        g_Pblk[blockIdx.x * 3 + threadIdx.x] = v;
    }
}

// ---------------- kernel 9: final reduction ----------------
__global__ void reduce_kernel(const float* __restrict__ out_b, float* out) {
    if (threadIdx.x < 3) {
        float s = 0.0f;
        for (int b = 0; b < 32; b++) s += g_Pblk[b * 3 + threadIdx.x];
        out[threadIdx.x] = s * (1.0f / (float)NN) + out_b[threadIdx.x];
    }
}

// ---------------- launch ----------------
extern "C" void kernel_launch(void* const* d_in, const int* in_sizes, int n_in,
                              void* d_out, int out_size) {
    (void)in_sizes; (void)n_in; (void)out_size;
    const float* t          = (const float*)d_in[0];
    const float* W_ih       = (const float*)d_in[1];
    const float* W_hh       = (const float*)d_in[2];
    const float* b_ih       = (const float*)d_in[3];
    const float* b_hh       = (const float*)d_in[4];
    const float* in_proj_w  = (const float*)d_in[5];
    const float* in_proj_b  = (const float*)d_in[6];
    const float* out_proj_w = (const float*)d_in[7];
    const float* out_proj_b = (const float*)d_in[8];
    const float* ln_w       = (const float*)d_in[9];
    const float* ln_b       = (const float*)d_in[10];
    const float* out_w      = (const float*)d_in[11];
    const float* out_b      = (const float*)d_in[12];
    float* out = (float*)d_out;

    lstm_kernel<<<1, 32>>>(t, W_ih, W_hh, b_ih, b_hh);
    qkv_kernel<<<(NN * 48 + 255) / 256, 256>>>(in_proj_w, in_proj_b);
    prepA_kernel<<<GRIDA, 256>>>();
    prepB_kernel<<<1, 64>>>();
    agg_kernel<<<GRIDA, 1024>>>();
    combine_kernel<<<(NHEAD * NF * 5 + 255) / 256, 256>>>();
    dim3 tg(NN / 256, NHEAD);
    tquery_kernel<<<tg, 256>>>();
    dim3 ag(NN / 64, SLICES);
    attn_kernel<<<ag, 256>>>();
    finalize_kernel<<<NN / 256, 256>>>(out_proj_w, out_proj_b, ln_w, ln_b, out_w);
    reduce_kernel<<<1, 32>>>(out_b, out);
}

// round 3
// speedup vs baseline: 1.2527x; 1.2527x over previous
#include <cuda_runtime.h>

#define NN 8192
#define HH 16
#define NHEAD 4
#define SLICES 8
#define TILE 256

// ---------------- device scratch (no allocations allowed) ----------------
__device__ float  g_Hseq[NN * HH];            // LSTM hidden states
__device__ float4 g_Q[NN * NHEAD];            // pre-scaled queries (x 0.5)
__device__ float4 g_K[NN * NHEAD];
__device__ float4 g_V[NN * NHEAD];
__device__ float  g_Pden[SLICES * NN * NHEAD];   // partial softmax denominators
__device__ float4 g_Pctx[SLICES * NN * NHEAD];   // partial weighted V sums
__device__ float  g_Pblk[32 * 3];                // per-block readout partial sums

__device__ __forceinline__ float tanh_fast(float x) {
    float y;
    asm("tanh.approx.f32 %0, %1;" : "=f"(y) : "f"(x));
    return y;
}

// ---------------- kernel 1: serial LSTM ----------------
// 1024 threads: all warps cooperatively stage t into shared, then warp 0
// runs the serial recurrence. Lane L (<16) computes gate rows L (i) and
// L+32 (g); lane L+16 computes rows L+16 (f) and L+48 (o).
__global__ void __launch_bounds__(1024, 1)
lstm_kernel(const float* __restrict__ t,
            const float* __restrict__ W_ih,
            const float* __restrict__ W_hh,
            const float* __restrict__ b_ih,
            const float* __restrict__ b_hh) {
    __shared__ float tsh[NN];
    for (int i = threadIdx.x; i < NN; i += 1024) tsh[i] = t[i];
    __syncthreads();
    if (threadIdx.x >= 32) return;

    const int lane = threadIdx.x;
    const int r1 = lane, r2 = lane + 32;
    float w1[HH], w2[HH];
#pragma unroll
    for (int k = 0; k < HH; k++) {
        w1[k] = W_hh[r1 * HH + k];
        w2[k] = W_hh[r2 * HH + k];
    }
    const float wi1 = W_ih[r1], wi2 = W_ih[r2];
    const float bb1 = b_ih[r1] + b_hh[r1];
    const float bb2 = b_ih[r2] + b_hh[r2];

    float h[HH];
#pragma unroll
    for (int k = 0; k < HH; k++) h[k] = 0.0f;
    float c = 0.0f;
    const bool lo = (lane < 16);
    const int peer = (lane & 15) + 16;

    for (int step = 0; step < NN; step++) {
        const float x = tsh[step];
        // gate pre-activations: 4 accumulators each to shorten dep chain
        float g1a = fmaf(wi1, x, bb1), g1b = 0.0f, g1c = 0.0f, g1d = 0.0f;
        float g2a = fmaf(wi2, x, bb2), g2b = 0.0f, g2c = 0.0f, g2d = 0.0f;
#pragma unroll
        for (int k = 0; k < HH; k += 4) {
            g1a = fmaf(w1[k],     h[k],     g1a);
            g1b = fmaf(w1[k + 1], h[k + 1], g1b);
            g1c = fmaf(w1[k + 2], h[k + 2], g1c);
            g1d = fmaf(w1[k + 3], h[k + 3], g1d);
            g2a = fmaf(w2[k],     h[k],     g2a);
            g2b = fmaf(w2[k + 1], h[k + 1], g2b);
            g2c = fmaf(w2[k + 2], h[k + 2], g2c);
            g2d = fmaf(w2[k + 3], h[k + 3], g2d);
        }
        const float g1 = (g1a + g1b) + (g1c + g1d);
        const float g2 = (g2a + g2b) + (g2c + g2d);

        // a1 = sigmoid(g1) = 0.5*tanh(0.5*g1)+0.5   (i for lanes<16, f otherwise)
        const float a1 = fmaf(0.5f, tanh_fast(0.5f * g1), 0.5f);
        // a2: tanh(g2) for lanes<16 (g-gate), sigmoid(g2) for 16-31 (o-gate)
        const float s2 = lo ? g2 : (0.5f * g2);
        const float th2 = tanh_fast(s2);
        const float a2 = lo ? th2 : fmaf(0.5f, th2, 0.5f);

        // lanes 0-15 fetch f, o from lanes 16-31
        const float fg = __shfl_sync(0xffffffffu, a1, peer);
        const float og = __shfl_sync(0xffffffffu, a2, peer);

        c = fmaf(fg, c, a1 * a2);                 // c = f*c + i*g
        const float hn = og * tanh_fast(c);

        if (lane < 16) g_Hseq[step * HH + lane] = hn;

#pragma unroll
        for (int k = 0; k < HH; k++)
            h[k] = __shfl_sync(0xffffffffu, hn, k);
    }
}

// ---------------- kernel 2: QKV projection ----------------
__global__ void qkv_kernel(const float* __restrict__ in_proj_w,
                           const float* __restrict__ in_proj_b) {
    const int idx = blockIdx.x * blockDim.x + threadIdx.x;
    if (idx >= NN * 48) return;
    const int n = idx / 48;
    const int j = idx % 48;
    const float* hr = g_Hseq + n * HH;
    float acc = in_proj_b[j];
#pragma unroll
    for (int k = 0; k < HH; k++)
        acc = fmaf(__ldg(in_proj_w + j * HH + k), hr[k], acc);

    if (j < 16)       ((float*)g_Q)[n * HH + j]        = acc * 0.5f;  // 1/sqrt(HD)
    else if (j < 32)  ((float*)g_K)[n * HH + (j - 16)] = acc;
    else              ((float*)g_V)[n * HH + (j - 32)] = acc;
}

// ---------------- kernel 3: exact attention (scores bounded; no max-shift) -
__global__ void attn_kernel() {
    __shared__ float4 Ksh[TILE * NHEAD];
    __shared__ float4 Vsh[TILE * NHEAD];

    const int tid = threadIdx.x;
    const int h   = tid >> 6;
    const int ql  = tid & 63;
    const int q   = blockIdx.x * 64 + ql;
    const int s   = blockIdx.y;

    const float4 qv = g_Q[q * NHEAD + h];
    float den = 0.0f;
    float4 acc = make_float4(0.0f, 0.0f, 0.0f, 0.0f);

    const int kbase0 = s * (NN / SLICES);
    for (int tile = 0; tile < (NN / SLICES) / TILE; tile++) {
        const int kb = kbase0 + tile * TILE;
        __syncthreads();
#pragma unroll
        for (int r = 0; r < 4; r++) {
            Ksh[tid + 256 * r] = g_K[kb * NHEAD + tid + 256 * r];
            Vsh[tid + 256 * r] = g_V[kb * NHEAD + tid + 256 * r];
        }
        __syncthreads();

#pragma unroll 4
        for (int kk = 0; kk < TILE; kk++) {
            const float4 kvv = Ksh[kk * NHEAD + h];
            float sc = qv.x * kvv.x;
            sc = fmaf(qv.y, kvv.y, sc);
            sc = fmaf(qv.z, kvv.z, sc);
            sc = fmaf(qv.w, kvv.w, sc);
            const float p = __expf(sc);
            den += p;
            const float4 vv = Vsh[kk * NHEAD + h];
            acc.x = fmaf(p, vv.x, acc.x);
            acc.y = fmaf(p, vv.y, acc.y);
            acc.z = fmaf(p, vv.z, acc.z);
            acc.w = fmaf(p, vv.w, acc.w);
        }
    }

    const int o = (s * NN + q) * NHEAD + h;
    g_Pden[o] = den;
    g_Pctx[o] = acc;
}

// ---------------- kernel 4: combine + out_proj + residual + LN + readout --
__global__ void finalize_kernel(const float* __restrict__ out_proj_w,
                                const float* __restrict__ out_proj_b,
                                const float* __restrict__ ln_w,
                                const float* __restrict__ ln_b,
                                const float* __restrict__ out_w) {
    const int q = blockIdx.x * 256 + threadIdx.x;

    float ctx[HH];
#pragma unroll
    for (int h = 0; h < NHEAD; h++) {
        float den = 0.0f;
        float4 a = make_float4(0.0f, 0.0f, 0.0f, 0.0f);
#pragma unroll
        for (int s = 0; s < SLICES; s++) {
            const int o = (s * NN + q) * NHEAD + h;
            den += g_Pden[o];
            const float4 p = g_Pctx[o];
            a.x += p.x; a.y += p.y; a.z += p.z; a.w += p.w;
        }
        const float inv = __fdividef(1.0f, den);
        ctx[h * 4 + 0] = a.x * inv;
        ctx[h * 4 + 1] = a.y * inv;
        ctx[h * 4 + 2] = a.z * inv;
        ctx[h * 4 + 3] = a.w * inv;
    }

    // out_proj + residual
    float y[HH];
#pragma unroll
    for (int r = 0; r < HH; r++) {
        float t = out_proj_b[r];
#pragma unroll
        for (int cc = 0; cc < HH; cc++)
            t = fmaf(__ldg(out_proj_w + r * HH + cc), ctx[cc], t);
        y[r] = t + g_Hseq[q * HH + r];
    }

    // LayerNorm over 16
    float mu = 0.0f;
#pragma unroll
    for (int r = 0; r < HH; r++) mu += y[r];
    mu *= (1.0f / HH);
    float var = 0.0f;
#pragma unroll
    for (int r = 0; r < HH; r++) {
        const float d = y[r] - mu;
        var = fmaf(d, d, var);
    }
    var *= (1.0f / HH);
    const float rstd = rsqrtf(var + 1e-5f);

    float z[HH];
#pragma unroll
    for (int r = 0; r < HH; r++)
        z[r] = (y[r] - mu) * rstd * ln_w[r] + ln_b[r];

    // readout (out_b added once at the end in reduce_kernel)
    float raw[3];
#pragma unroll
    for (int j = 0; j < 3; j++) {
        float t = 0.0f;
#pragma unroll
        for (int r = 0; r < HH; r++)
            t = fmaf(__ldg(out_w + j * HH + r), z[r], t);
        raw[j] = t;
    }

    __shared__ float wsum[8][3];
    const int lane = threadIdx.x & 31;
    const int wid  = threadIdx.x >> 5;
#pragma unroll
    for (int j = 0; j < 3; j++) {
        float v = raw[j];
#pragma unroll
        for (int off = 16; off > 0; off >>= 1)
            v += __shfl_xor_sync(0xffffffffu, v, off);
        if (lane == 0) wsum[wid][j] = v;
    }
    __syncthreads();
    if (threadIdx.x < 3) {
        float v = 0.0f;
#pragma unroll
        for (int w = 0; w < 8; w++) v += wsum[w][threadIdx.x];
        g_Pblk[blockIdx.x * 3 + threadIdx.x] = v;
    }
}

// ---------------- kernel 5: final reduction ----------------
__global__ void reduce_kernel(const float* __restrict__ out_b, float* out) {
    if (threadIdx.x < 3) {
        float s = 0.0f;
        for (int b = 0; b < 32; b++) s += g_Pblk[b * 3 + threadIdx.x];
        out[threadIdx.x] = s * (1.0f / (float)NN) + out_b[threadIdx.x];
    }
}

// ---------------- launch ----------------
extern "C" void kernel_launch(void* const* d_in, const int* in_sizes, int n_in,
                              void* d_out, int out_size) {
    (void)in_sizes; (void)n_in; (void)out_size;
    const float* t          = (const float*)d_in[0];
    const float* W_ih       = (const float*)d_in[1];
    const float* W_hh       = (const float*)d_in[2];
    const float* b_ih       = (const float*)d_in[3];
    const float* b_hh       = (const float*)d_in[4];
    const float* in_proj_w  = (const float*)d_in[5];
    const float* in_proj_b  = (const float*)d_in[6];
    const float* out_proj_w = (const float*)d_in[7];
    const float* out_proj_b = (const float*)d_in[8];
    const float* ln_w       = (const float*)d_in[9];
    const float* ln_b       = (const float*)d_in[10];
    const float* out_w      = (const float*)d_in[11];
    const float* out_b      = (const float*)d_in[12];
    float* out = (float*)d_out;

    lstm_kernel<<<1, 1024>>>(t, W_ih, W_hh, b_ih, b_hh);
    qkv_kernel<<<(NN * 48 + 255) / 256, 256>>>(in_proj_w, in_proj_b);
    dim3 ag(NN / 64, SLICES);
    attn_kernel<<<ag, 256>>>();
    finalize_kernel<<<NN / 256, 256>>>(out_proj_w, out_proj_b, ln_w, ln_b, out_w);
    reduce_kernel<<<1, 32>>>(out_b, out);
}